// round 14
// baseline (speedup 1.0000x reference)
#include <cuda_runtime.h>
#include <cuda_fp16.h>
#include <cstdint>

// Problem constants (shapes fixed by setup_inputs)
#define NMAX   50000
#define EAMAX  850000     // E + N self loops
#define F_IN   128
#define HC     256        // heads*out_ch layer 1
#define H1     4
#define SCB    1024       // scan block size

// gemm tiling (fp16 HMMA)
#define BMt 128
#define BNt 128
#define KC  16            // k per chunk, 8 chunks
#define AST 24            // A smem stride in halves
#define WST 136           // W smem stride in halves

typedef unsigned long long u64;

// ---------------- scratch (static __device__, allocation-free) ----------------
__device__ __half   g_h1h[NMAX * HC];      // layer-1 features, fp16
__device__ __half   g_Wth[F_IN * HC];      // W1 transposed [k][c], fp16
__device__ float    g_as1[NMAX * H1];
__device__ float    g_ad1[NMAX * H1];
__device__ int      g_src[EAMAX];
__device__ int      g_dst[EAMAX];
__device__ int      g_cnt[NMAX];
__device__ int      g_rowstart[NMAX];
__device__ int      g_fill[NMAX];
__device__ int      g_csr_src[EAMAX];
__device__ int      g_bsum[64];
__device__ int      g_boff[64];
__device__ float    g_h2[NMAX * 2];
__device__ float    g_as2[NMAX];
__device__ float    g_ad2[NMAX];
__device__ int      g_is64;

// ---------------- helpers ----------------
__device__ __forceinline__ float lrelu(float x) { return x > 0.f ? x : 0.2f * x; }

__device__ __forceinline__ uint32_t h2u(__half2 h) {
    return *reinterpret_cast<uint32_t*>(&h);
}
__device__ __forceinline__ uint32_t packh2(float lo, float hi) {
    return h2u(__float22half2_rn(make_float2(lo, hi)));
}
__device__ __forceinline__ uint32_t sm2u32(const void* p) {
    return (uint32_t)__cvta_generic_to_shared(p);
}
__device__ __forceinline__ void ldsm_x4(uint32_t* r, uint32_t addr) {
    asm volatile("ldmatrix.sync.aligned.m8n8.x4.shared.b16 {%0,%1,%2,%3}, [%4];"
                 : "=r"(r[0]), "=r"(r[1]), "=r"(r[2]), "=r"(r[3]) : "r"(addr));
}
__device__ __forceinline__ void ldsm_x4_t(uint32_t* r, uint32_t addr) {
    asm volatile("ldmatrix.sync.aligned.m8n8.x4.trans.shared.b16 {%0,%1,%2,%3}, [%4];"
                 : "=r"(r[0]), "=r"(r[1]), "=r"(r[2]), "=r"(r[3]) : "r"(addr));
}
__device__ __forceinline__ void mma16816(float* d, const uint32_t* a,
                                         uint32_t b0, uint32_t b1) {
    asm volatile(
        "mma.sync.aligned.m16n8k16.row.col.f32.f16.f16.f32 "
        "{%0,%1,%2,%3}, {%4,%5,%6,%7}, {%8,%9}, {%0,%1,%2,%3};"
        : "+f"(d[0]), "+f"(d[1]), "+f"(d[2]), "+f"(d[3])
        : "r"(a[0]), "r"(a[1]), "r"(a[2]), "r"(a[3]), "r"(b0), "r"(b1));
}

// ---------------- setup kernels ----------------
__global__ void detect_kernel(const void* ei, int twoE, long long N) {
    int lane = threadIdx.x;
    const long long* p = (const long long*)ei;
    int m = twoE < 64 ? twoE : 64;
    int bad = 0;
#pragma unroll
    for (int r = 0; r < 2; r++) {
        int i = lane + 32 * r;
        if (i < m) {
            long long v = p[i];
            if (v < 0 || v >= N) bad = 1;
        }
    }
    unsigned anybad = __ballot_sync(0xFFFFFFFFu, bad);
    if (lane == 0) g_is64 = (anybad == 0u) ? 1 : 0;
}

__global__ void zerocnt_kernel(int N) {
    int i = blockIdx.x * blockDim.x + threadIdx.x;
    if (i < N) g_cnt[i] = 0;
}

// Wt transpose (fp32 -> fp16) + zero as1/ad1 (branch A prologue, independent)
__global__ void wtzero_kernel(const float* __restrict__ W1, int N) {
    int i = blockIdx.x * blockDim.x + threadIdx.x;
    if (i < F_IN * HC) {
        int k = i / HC, c = i % HC;
        g_Wth[i] = __float2half_rn(W1[c * F_IN + k]);
    }
    if (i < N * H1) { g_as1[i] = 0.f; g_ad1[i] = 0.f; }
}

// split edge_index + self loops + fused dst histogram
__global__ void edges_hist_kernel(const void* ei, int E, int N) {
    int i = blockIdx.x * blockDim.x + threadIdx.x;
    int twoE = 2 * E;
    if (i < twoE) {
        int v;
        if (g_is64) v = (int)((const long long*)ei)[i];
        else        v = ((const int*)ei)[i];
        if (i < E) g_src[i] = v;
        else {
            g_dst[i - E] = v;
            atomicAdd(&g_cnt[v], 1);
        }
    } else if (i < twoE + N) {
        int n = i - twoE;
        g_src[E + n] = n;
        g_dst[E + n] = n;
        atomicAdd(&g_cnt[n], 1);
    }
}

// hierarchical scan
__global__ void scan1_kernel(int N) {
    __shared__ int sp[SCB];
    int t = threadIdx.x;
    int i = blockIdx.x * SCB + t;
    int val = (i < N) ? g_cnt[i] : 0;
    sp[t] = val;
    __syncthreads();
    for (int off = 1; off < SCB; off <<= 1) {
        int v = (t >= off) ? sp[t - off] : 0;
        __syncthreads();
        sp[t] += v;
        __syncthreads();
    }
    if (i < N) g_rowstart[i] = sp[t] - val;
    if (t == SCB - 1) g_bsum[blockIdx.x] = sp[t];
}

__global__ void scan2_kernel(int nb) {
    __shared__ int sp[256];
    int t = threadIdx.x;
    int val = (t < nb) ? g_bsum[t] : 0;
    sp[t] = val;
    __syncthreads();
    for (int off = 1; off < 256; off <<= 1) {
        int v = (t >= off) ? sp[t - off] : 0;
        __syncthreads();
        sp[t] += v;
        __syncthreads();
    }
    if (t < nb) g_boff[t] = sp[t] - val;
}

__global__ void scan3_kernel(int N) {
    int i = blockIdx.x * blockDim.x + threadIdx.x;
    if (i < N) {
        int v = g_rowstart[i] + g_boff[i >> 10];
        g_rowstart[i] = v;
        g_fill[i]     = v;
    }
}

__global__ void scatter_kernel(int EA) {
    int e = blockIdx.x * blockDim.x + threadIdx.x;
    if (e >= EA) return;
    int d = g_dst[e];
    int pos = atomicAdd(&g_fill[d], 1);
    g_csr_src[pos] = g_src[e];
}

// ------------- h1 = x @ W1^T : fp16 HMMA (m16n8k16) + ldmatrix --------------
__global__ void __launch_bounds__(256, 2) gemm1_kernel(const float* __restrict__ x, int N,
                                                       const float* __restrict__ att_src,
                                                       const float* __restrict__ att_dst) {
    __shared__ __half Asm[2][128 * AST];   // [node][k] row-major, stride 24 halves
    __shared__ __half Wsm[2][KC * WST];    // [k][c] row-major, stride 136 halves
    int t    = threadIdx.x;
    int w    = t >> 5;
    int lane = t & 31;
    int wm   = w & 3;
    int wn   = w >> 2;
    int n0   = blockIdx.x * BMt;
    int c0   = blockIdx.y * BNt;

    int rowA = t & 127, jA = t >> 7;
    bool aok = (n0 + rowA) < N;
    const float* xrow = &x[(size_t)(n0 + rowA) * F_IN + jA * 8];
    int kW = t >> 4, cW = (t & 15) * 8;
    const __half* wsrc = &g_Wth[(size_t)kW * HC + c0 + cW];
    __half* adst0 = &Asm[0][rowA * AST + jA * 8];
    __half* adst1 = &Asm[1][rowA * AST + jA * 8];
    __half* wdst0 = &Wsm[0][kW * WST + cW];
    __half* wdst1 = &Wsm[1][kW * WST + cW];

    uint32_t aaddr0 = sm2u32(&Asm[0][(wm * 32 + (lane & 15)) * AST + (lane >> 4) * 8]);
    uint32_t aaddr1 = sm2u32(&Asm[1][(wm * 32 + (lane & 15)) * AST + (lane >> 4) * 8]);
    uint32_t baddr0 = sm2u32(&Wsm[0][(lane & 15) * WST + wn * 64 + (lane >> 4) * 8]);
    uint32_t baddr1 = sm2u32(&Wsm[1][(lane & 15) * WST + wn * 64 + (lane >> 4) * 8]);

    float acc[2][8][4];
#pragma unroll
    for (int mi = 0; mi < 2; mi++)
#pragma unroll
        for (int ni = 0; ni < 8; ni++)
#pragma unroll
            for (int j = 0; j < 4; j++) acc[mi][ni][j] = 0.f;

    {
        float4 q0 = make_float4(0.f, 0.f, 0.f, 0.f), q1 = q0;
        if (aok) { q0 = *(const float4*)&xrow[0]; q1 = *(const float4*)&xrow[4]; }
        uint4 pa;
        pa.x = packh2(q0.x, q0.y);
        pa.y = packh2(q0.z, q0.w);
        pa.z = packh2(q1.x, q1.y);
        pa.w = packh2(q1.z, q1.w);
        *(uint4*)adst0 = pa;
        *(uint4*)wdst0 = *(const uint4*)wsrc;
        __syncthreads();
    }

    for (int it = 0; it < 8; it++) {
        int cur = it & 1;
        float4 q0 = make_float4(0.f, 0.f, 0.f, 0.f), q1 = q0;
        uint4 wv = make_uint4(0u, 0u, 0u, 0u);
        if (it < 7) {
            int k0 = (it + 1) * KC;
            if (aok) { q0 = *(const float4*)&xrow[k0]; q1 = *(const float4*)&xrow[k0 + 4]; }
            wv = *(const uint4*)(wsrc + (size_t)k0 * HC);
        }
        uint32_t a[2][4], b[4][4];
        uint32_t aa = cur ? aaddr1 : aaddr0;
        uint32_t bb = cur ? baddr1 : baddr0;
        ldsm_x4(a[0], aa);
        ldsm_x4(a[1], aa + 16 * AST * 2);
#pragma unroll
        for (int g = 0; g < 4; g++)
            ldsm_x4_t(b[g], bb + g * 16 * 2);
#pragma unroll
        for (int ni = 0; ni < 8; ni++) {
            uint32_t b0 = b[ni >> 1][(ni & 1) * 2 + 0];
            uint32_t b1 = b[ni >> 1][(ni & 1) * 2 + 1];
            mma16816(acc[0][ni], a[0], b0, b1);
            mma16816(acc[1][ni], a[1], b0, b1);
        }
        if (it < 7) {
            uint4 pa;
            pa.x = packh2(q0.x, q0.y);
            pa.y = packh2(q0.z, q0.w);
            pa.z = packh2(q1.x, q1.y);
            pa.w = packh2(q1.z, q1.w);
            *(uint4*)(cur ? adst0 : adst1) = pa;
            *(uint4*)(cur ? wdst0 : wdst1) = wv;
            __syncthreads();
        }
    }

    // epilogue: store h1 (fp16) + partial attention dots (one head per warp)
    int r  = lane >> 2;
    int kq = lane & 3;
    int hbase = (c0 + wn * 64) >> 6;
    float sA[2][2] = {{0.f, 0.f}, {0.f, 0.f}};
    float dA[2][2] = {{0.f, 0.f}, {0.f, 0.f}};
#pragma unroll
    for (int mi = 0; mi < 2; mi++) {
        int row_lo = n0 + wm * 32 + mi * 16 + r;
        int row_hi = row_lo + 8;
#pragma unroll
        for (int ni = 0; ni < 8; ni++) {
            const float* dd = acc[mi][ni];
            int col = c0 + wn * 64 + ni * 8 + 2 * kq;
            if (row_lo < N) {
                uint32_t pv = packh2(dd[0], dd[1]);
                *(uint32_t*)&g_h1h[(size_t)row_lo * HC + col] = pv;
            }
            if (row_hi < N) {
                uint32_t pv = packh2(dd[2], dd[3]);
                *(uint32_t*)&g_h1h[(size_t)row_hi * HC + col] = pv;
            }
            float2 as = *(const float2*)&att_src[col];
            float2 ad = *(const float2*)&att_dst[col];
            sA[mi][0] += dd[0] * as.x + dd[1] * as.y;
            sA[mi][1] += dd[2] * as.x + dd[3] * as.y;
            dA[mi][0] += dd[0] * ad.x + dd[1] * ad.y;
            dA[mi][1] += dd[2] * ad.x + dd[3] * ad.y;
        }
    }
#pragma unroll
    for (int mi = 0; mi < 2; mi++)
#pragma unroll
        for (int j = 0; j < 2; j++) {
            sA[mi][j] += __shfl_down_sync(0xFFFFFFFFu, sA[mi][j], 2, 4);
            sA[mi][j] += __shfl_down_sync(0xFFFFFFFFu, sA[mi][j], 1, 4);
            dA[mi][j] += __shfl_down_sync(0xFFFFFFFFu, dA[mi][j], 2, 4);
            dA[mi][j] += __shfl_down_sync(0xFFFFFFFFu, dA[mi][j], 1, 4);
        }
    if (kq == 0) {
#pragma unroll
        for (int mi = 0; mi < 2; mi++)
#pragma unroll
            for (int j = 0; j < 2; j++) {
                int node = n0 + wm * 32 + mi * 16 + j * 8 + r;
                if (node < N) {
                    atomicAdd(&g_as1[node * H1 + hbase], sA[mi][j]);
                    atomicAdd(&g_ad1[node * H1 + hbase], dA[mi][j]);
                }
            }
    }
}

// ---- fused layer-1 softmax+aggregation+layer-2 projection -------------------
// One WARP per destination node; fp16 gather (16B/lane/edge), 4-edge unroll.
__global__ void agg1_kernel(const float* __restrict__ b1,
                            const float* __restrict__ W2,
                            const float* __restrict__ att_src2,
                            const float* __restrict__ att_dst2, int N) {
    int gid  = blockIdx.x * blockDim.x + threadIdx.x;
    int n    = gid >> 5;
    int lane = gid & 31;
    if (n >= N) return;
    int start = g_rowstart[n];
    int deg   = g_cnt[n];
    int cbase = lane * 8;
    int h     = lane >> 3;
    float ad  = g_ad1[n * 4 + h];

    float A[8];
#pragma unroll
    for (int j = 0; j < 8; j++) A[j] = 0.f;
    float den = 0.f;

    int e = 0;
    for (; e + 4 <= deg; e += 4) {
        int s0 = g_csr_src[start + e + 0];
        int s1 = g_csr_src[start + e + 1];
        int s2 = g_csr_src[start + e + 2];
        int s3 = g_csr_src[start + e + 3];
        float a0 = g_as1[s0 * 4 + h];
        float a1 = g_as1[s1 * 4 + h];
        float a2 = g_as1[s2 * 4 + h];
        float a3 = g_as1[s3 * 4 + h];
        uint4 v0 = *(const uint4*)&g_h1h[(size_t)s0 * HC + cbase];
        uint4 v1 = *(const uint4*)&g_h1h[(size_t)s1 * HC + cbase];
        uint4 v2 = *(const uint4*)&g_h1h[(size_t)s2 * HC + cbase];
        uint4 v3 = *(const uint4*)&g_h1h[(size_t)s3 * HC + cbase];
        float x0 = __expf(lrelu(a0 + ad));
        float x1 = __expf(lrelu(a1 + ad));
        float x2 = __expf(lrelu(a2 + ad));
        float x3 = __expf(lrelu(a3 + ad));
        den += (x0 + x1) + (x2 + x3);
        const uint32_t* vv[4] = {&v0.x, &v1.x, &v2.x, &v3.x};
        float xs[4] = {x0, x1, x2, x3};
#pragma unroll
        for (int q = 0; q < 4; q++) {
            float xq = xs[q];
#pragma unroll
            for (int j = 0; j < 4; j++) {
                float2 f = __half22float2(*(const __half2*)&vv[q][j]);
                A[2 * j + 0] += xq * f.x;
                A[2 * j + 1] += xq * f.y;
            }
        }
    }
    for (; e < deg; e++) {
        int s0 = g_csr_src[start + e];
        float a0 = g_as1[s0 * 4 + h];
        uint4 v0 = *(const uint4*)&g_h1h[(size_t)s0 * HC + cbase];
        float x0 = __expf(lrelu(a0 + ad));
        den += x0;
        const uint32_t* vv = &v0.x;
#pragma unroll
        for (int j = 0; j < 4; j++) {
            float2 f = __half22float2(*(const __half2*)&vv[j]);
            A[2 * j + 0] += x0 * f.x;
            A[2 * j + 1] += x0 * f.y;
        }
    }

    float inv = 1.f / (den + 1e-16f);
    const float4* b4 = (const float4*)&b1[cbase];
    float4 bb0 = b4[0], bb1 = b4[1];
    float y[8];
    y[0] = fmaxf(A[0] * inv + bb0.x, 0.f);
    y[1] = fmaxf(A[1] * inv + bb0.y, 0.f);
    y[2] = fmaxf(A[2] * inv + bb0.z, 0.f);
    y[3] = fmaxf(A[3] * inv + bb0.w, 0.f);
    y[4] = fmaxf(A[4] * inv + bb1.x, 0.f);
    y[5] = fmaxf(A[5] * inv + bb1.y, 0.f);
    y[6] = fmaxf(A[6] * inv + bb1.z, 0.f);
    y[7] = fmaxf(A[7] * inv + bb1.w, 0.f);

    const float4* w0q = (const float4*)&W2[cbase];
    const float4* w1q = (const float4*)&W2[HC + cbase];
    float4 wa0 = w0q[0], wa1 = w0q[1];
    float4 wb0 = w1q[0], wb1 = w1q[1];
    float p0 = y[0] * wa0.x + y[1] * wa0.y + y[2] * wa0.z + y[3] * wa0.w
             + y[4] * wa1.x + y[5] * wa1.y + y[6] * wa1.z + y[7] * wa1.w;
    float p1 = y[0] * wb0.x + y[1] * wb0.y + y[2] * wb0.z + y[3] * wb0.w
             + y[4] * wb1.x + y[5] * wb1.y + y[6] * wb1.z + y[7] * wb1.w;
#pragma unroll
    for (int o = 16; o; o >>= 1) {
        p0 += __shfl_down_sync(0xFFFFFFFFu, p0, o);
        p1 += __shfl_down_sync(0xFFFFFFFFu, p1, o);
    }
    if (lane == 0) {
        g_h2[n * 2 + 0] = p0;
        g_h2[n * 2 + 1] = p1;
        g_as2[n] = p0 * att_src2[0] + p1 * att_src2[1];
        g_ad2[n] = p0 * att_dst2[0] + p1 * att_dst2[1];
    }
}

// ---------------- fused layer-2: 8 lanes per destination node ---------------
__global__ void agg2_kernel(const float* __restrict__ b2,
                            float* __restrict__ out, int N) {
    int gid  = blockIdx.x * blockDim.x + threadIdx.x;
    int n    = gid >> 3;
    int lane = gid & 7;
    if (n >= N) return;
    int start = g_rowstart[n];
    int deg   = g_cnt[n];
    float adv = g_ad2[n];

    float den = 0.f, a0 = 0.f, a1 = 0.f;
    for (int e = lane; e < deg; e += 8) {
        int s  = g_csr_src[start + e];
        float ex = __expf(lrelu(g_as2[s] + adv));
        den += ex;
        float2 hv = *(const float2*)&g_h2[s * 2];
        a0 += ex * hv.x;
        a1 += ex * hv.y;
    }
#pragma unroll
    for (int o = 4; o; o >>= 1) {
        den += __shfl_xor_sync(0xFFFFFFFFu, den, o, 8);
        a0  += __shfl_xor_sync(0xFFFFFFFFu, a0, o, 8);
        a1  += __shfl_xor_sync(0xFFFFFFFFu, a1, o, 8);
    }
    if (lane == 0) {
        float inv = 1.f / (den + 1e-16f);
        out[n * 2 + 0] = a0 * inv + b2[0];
        out[n * 2 + 1] = a1 * inv + b2[1];
    }
}

// ---------------- launch ----------------
extern "C" void kernel_launch(void* const* d_in, const int* in_sizes, int n_in,
                              void* d_out, int out_size) {
    const float* x        = (const float*)d_in[0];
    const void*  ei       = d_in[1];
    const float* W1       = (const float*)d_in[2];
    const float* att_src1 = (const float*)d_in[3];
    const float* att_dst1 = (const float*)d_in[4];
    const float* b1       = (const float*)d_in[5];
    const float* W2       = (const float*)d_in[6];
    const float* att_src2 = (const float*)d_in[7];
    const float* att_dst2 = (const float*)d_in[8];
    const float* b2       = (const float*)d_in[9];

    int N  = in_sizes[0] / F_IN;
    int E  = in_sizes[1] / 2;
    int EA = E + N;

    const int B = 256;
    int gE = (EA + B - 1) / B;
    int nb = (N + SCB - 1) / SCB;

    // Side stream + events (created once, host-side only).
    static cudaStream_t sB = 0;
    static cudaEvent_t  ev0 = 0, evB = 0;
    if (!sB) {
        cudaStreamCreateWithFlags(&sB, cudaStreamNonBlocking);
        cudaEventCreateWithFlags(&ev0, cudaEventDisableTiming);
        cudaEventCreateWithFlags(&evB, cudaEventDisableTiming);
    }

    // -------- fork FIRST: branch A has no upstream deps, starts at t=0 ------
    cudaEventRecord(ev0, 0);
    cudaStreamWaitEvent(sB, ev0, 0);
    wtzero_kernel<<<(N * H1 + B - 1) / B, B, 0, sB>>>(W1, N);              // branch A
    dim3 gg((N + BMt - 1) / BMt, HC / BNt);
    gemm1_kernel<<<gg, 256, 0, sB>>>(x, N, att_src1, att_dst1);            // (profiled)
    cudaEventRecord(evB, sB);

    // -------- stream 0: edge-side prologue + CSR build (overlaps gemm) ------
    detect_kernel<<<1, 32>>>(ei, 2 * E, (long long)N);
    zerocnt_kernel<<<(N + B - 1) / B, B>>>(N);
    edges_hist_kernel<<<(2 * E + N + B - 1) / B, B>>>(ei, E, N);
    scan1_kernel<<<nb, SCB>>>(N);
    scan2_kernel<<<1, 256>>>(nb);
    scan3_kernel<<<(N + B - 1) / B, B>>>(N);
    scatter_kernel<<<gE, B>>>(EA);

    // -------- join + aggregation --------
    cudaStreamWaitEvent(0, evB, 0);
    agg1_kernel<<<(N * 32 + B - 1) / B, B>>>(b1, W2, att_src2, att_dst2, N);
    agg2_kernel<<<(N * 8 + B - 1) / B, B>>>(b2, (float*)d_out, N);
}

// round 17
// speedup vs baseline: 1.0281x; 1.0281x over previous
#include <cuda_runtime.h>
#include <cuda_fp16.h>
#include <cstdint>

// Problem constants (shapes fixed by setup_inputs)
#define NMAX   50000
#define EAMAX  850000     // E + N self loops
#define F_IN   128
#define HC     256        // heads*out_ch layer 1
#define H1     4
#define SCB    1024       // scan block size

// gemm tiling (fp16 HMMA, cp.async 4-stage pipeline)
#define BMt 128
#define BNt 128
#define KC  16            // k per chunk, 8 chunks
#define AST 24            // A smem stride in halves
#define WST 136           // W smem stride in halves
#define NSTG 4

typedef unsigned long long u64;

// ---------------- scratch (static __device__, allocation-free) ----------------
__device__ __half   g_xh[(NMAX + 128) * F_IN];   // x in fp16 (padded rows zeroed)
__device__ __half   g_h1h[NMAX * HC];            // layer-1 features, fp16
__device__ __half   g_Wth[F_IN * HC];            // W1 transposed [k][c], fp16
__device__ float    g_as1[NMAX * H1];
__device__ float    g_ad1[NMAX * H1];
__device__ int      g_src[EAMAX];
__device__ int      g_dst[EAMAX];
__device__ int      g_cnt[NMAX];
__device__ int      g_rowstart[NMAX];
__device__ int      g_fill[NMAX];
__device__ int      g_csr_src[EAMAX];
__device__ int      g_bsum[64];
__device__ int      g_boff[64];
__device__ float    g_h2[NMAX * 2];
__device__ float    g_as2[NMAX];
__device__ float    g_ad2[NMAX];
__device__ int      g_is64;

// ---------------- helpers ----------------
__device__ __forceinline__ float lrelu(float x) { return x > 0.f ? x : 0.2f * x; }

__device__ __forceinline__ uint32_t h2u(__half2 h) {
    return *reinterpret_cast<uint32_t*>(&h);
}
__device__ __forceinline__ uint32_t packh2(float lo, float hi) {
    return h2u(__float22half2_rn(make_float2(lo, hi)));
}
__device__ __forceinline__ uint32_t sm2u32(const void* p) {
    return (uint32_t)__cvta_generic_to_shared(p);
}
__device__ __forceinline__ void cpasync16(uint32_t smem, const void* g) {
    asm volatile("cp.async.ca.shared.global [%0], [%1], 16;" :: "r"(smem), "l"(g));
}
#define CPCOMMIT() asm volatile("cp.async.commit_group;")
#define CPWAIT2()  asm volatile("cp.async.wait_group 2;")

__device__ __forceinline__ void ldsm_x4(uint32_t* r, uint32_t addr) {
    asm volatile("ldmatrix.sync.aligned.m8n8.x4.shared.b16 {%0,%1,%2,%3}, [%4];"
                 : "=r"(r[0]), "=r"(r[1]), "=r"(r[2]), "=r"(r[3]) : "r"(addr));
}
__device__ __forceinline__ void ldsm_x4_t(uint32_t* r, uint32_t addr) {
    asm volatile("ldmatrix.sync.aligned.m8n8.x4.trans.shared.b16 {%0,%1,%2,%3}, [%4];"
                 : "=r"(r[0]), "=r"(r[1]), "=r"(r[2]), "=r"(r[3]) : "r"(addr));
}
__device__ __forceinline__ void mma16816(float* d, const uint32_t* a,
                                         uint32_t b0, uint32_t b1) {
    asm volatile(
        "mma.sync.aligned.m16n8k16.row.col.f32.f16.f16.f32 "
        "{%0,%1,%2,%3}, {%4,%5,%6,%7}, {%8,%9}, {%0,%1,%2,%3};"
        : "+f"(d[0]), "+f"(d[1]), "+f"(d[2]), "+f"(d[3])
        : "r"(a[0]), "r"(a[1]), "r"(a[2]), "r"(a[3]), "r"(b0), "r"(b1));
}

// ---------------- setup kernels ----------------
__global__ void detect_kernel(const void* ei, int twoE, long long N) {
    int lane = threadIdx.x;
    const long long* p = (const long long*)ei;
    int m = twoE < 64 ? twoE : 64;
    int bad = 0;
#pragma unroll
    for (int r = 0; r < 2; r++) {
        int i = lane + 32 * r;
        if (i < m) {
            long long v = p[i];
            if (v < 0 || v >= N) bad = 1;
        }
    }
    unsigned anybad = __ballot_sync(0xFFFFFFFFu, bad);
    if (lane == 0) g_is64 = (anybad == 0u) ? 1 : 0;
}

__global__ void zerocnt_kernel(int N) {
    int i = blockIdx.x * blockDim.x + threadIdx.x;
    if (i < N) g_cnt[i] = 0;
}

// x fp32 -> fp16 (8 elements/thread) + zero pad rows
__global__ void xcvt_kernel(const float* __restrict__ x, int N) {
    int i = blockIdx.x * blockDim.x + threadIdx.x;    // 8-element groups
    int total = (N + 128) * F_IN / 8;
    if (i >= total) return;
    int base = i * 8;
    uint4 pa = make_uint4(0u, 0u, 0u, 0u);
    if (base < N * F_IN) {
        float4 q0 = *(const float4*)&x[base];
        float4 q1 = *(const float4*)&x[base + 4];
        pa.x = packh2(q0.x, q0.y);
        pa.y = packh2(q0.z, q0.w);
        pa.z = packh2(q1.x, q1.y);
        pa.w = packh2(q1.z, q1.w);
    }
    *(uint4*)&g_xh[base] = pa;
}

// Wt transpose (fp32 -> fp16) + zero as1/ad1
__global__ void wtzero_kernel(const float* __restrict__ W1, int N) {
    int i = blockIdx.x * blockDim.x + threadIdx.x;
    if (i < F_IN * HC) {
        int k = i / HC, c = i % HC;
        g_Wth[i] = __float2half_rn(W1[c * F_IN + k]);
    }
    if (i < N * H1) { g_as1[i] = 0.f; g_ad1[i] = 0.f; }
}

// split edge_index + self loops + fused dst histogram
__global__ void edges_hist_kernel(const void* ei, int E, int N) {
    int i = blockIdx.x * blockDim.x + threadIdx.x;
    int twoE = 2 * E;
    if (i < twoE) {
        int v;
        if (g_is64) v = (int)((const long long*)ei)[i];
        else        v = ((const int*)ei)[i];
        if (i < E) g_src[i] = v;
        else {
            g_dst[i - E] = v;
            atomicAdd(&g_cnt[v], 1);
        }
    } else if (i < twoE + N) {
        int n = i - twoE;
        g_src[E + n] = n;
        g_dst[E + n] = n;
        atomicAdd(&g_cnt[n], 1);
    }
}

// hierarchical scan
__global__ void scan1_kernel(int N) {
    __shared__ int sp[SCB];
    int t = threadIdx.x;
    int i = blockIdx.x * SCB + t;
    int val = (i < N) ? g_cnt[i] : 0;
    sp[t] = val;
    __syncthreads();
    for (int off = 1; off < SCB; off <<= 1) {
        int v = (t >= off) ? sp[t - off] : 0;
        __syncthreads();
        sp[t] += v;
        __syncthreads();
    }
    if (i < N) g_rowstart[i] = sp[t] - val;
    if (t == SCB - 1) g_bsum[blockIdx.x] = sp[t];
}

__global__ void scan2_kernel(int nb) {
    __shared__ int sp[256];
    int t = threadIdx.x;
    int val = (t < nb) ? g_bsum[t] : 0;
    sp[t] = val;
    __syncthreads();
    for (int off = 1; off < 256; off <<= 1) {
        int v = (t >= off) ? sp[t - off] : 0;
        __syncthreads();
        sp[t] += v;
        __syncthreads();
    }
    if (t < nb) g_boff[t] = sp[t] - val;
}

__global__ void scan3_kernel(int N) {
    int i = blockIdx.x * blockDim.x + threadIdx.x;
    if (i < N) {
        int v = g_rowstart[i] + g_boff[i >> 10];
        g_rowstart[i] = v;
        g_fill[i]     = v;
    }
}

__global__ void scatter_kernel(int EA) {
    int e = blockIdx.x * blockDim.x + threadIdx.x;
    if (e >= EA) return;
    int d = g_dst[e];
    int pos = atomicAdd(&g_fill[d], 1);
    g_csr_src[pos] = g_src[e];
}

// ------------- h1 = xh @ W1^T : fp16 HMMA + 4-stage cp.async pipeline -------
__global__ void __launch_bounds__(256, 2) gemm1_kernel(int N,
                                                       const float* __restrict__ att_src,
                                                       const float* __restrict__ att_dst) {
    __shared__ __half Asm[NSTG][128 * AST];   // [node][k], stride 24 halves
    __shared__ __half Wsm[NSTG][KC * WST];    // [k][c], stride 136 halves
    int t    = threadIdx.x;
    int w    = t >> 5;
    int lane = t & 31;
    int wm   = w & 3;
    int wn   = w >> 2;
    int n0   = blockIdx.x * BMt;
    int c0   = blockIdx.y * BNt;

    // staging assignment: A thread -> 16B of one row; W thread -> 16B of one k-row
    int rowA = t >> 1, jA = (t & 1) * 8;
    const __half* axsrc = &g_xh[(size_t)(n0 + rowA) * F_IN + jA];
    int kW = t >> 4, cW = (t & 15) * 8;
    const __half* wsrc = &g_Wth[(size_t)kW * HC + c0 + cW];

    uint32_t adst[NSTG], wdst[NSTG], aaddr[NSTG], baddr[NSTG];
#pragma unroll
    for (int s = 0; s < NSTG; s++) {
        adst[s]  = sm2u32(&Asm[s][rowA * AST + jA]);
        wdst[s]  = sm2u32(&Wsm[s][kW * WST + cW]);
        aaddr[s] = sm2u32(&Asm[s][(wm * 32 + (lane & 15)) * AST + (lane >> 4) * 8]);
        baddr[s] = sm2u32(&Wsm[s][(lane & 15) * WST + wn * 64 + (lane >> 4) * 8]);
    }

    float acc[2][8][4];
#pragma unroll
    for (int mi = 0; mi < 2; mi++)
#pragma unroll
        for (int ni = 0; ni < 8; ni++)
#pragma unroll
            for (int j = 0; j < 4; j++) acc[mi][ni][j] = 0.f;

    // prologue: stage chunks 0..2
#pragma unroll
    for (int s = 0; s < 3; s++) {
        cpasync16(adst[s], axsrc + s * KC);
        cpasync16(wdst[s], wsrc + (size_t)s * KC * HC);
        CPCOMMIT();
    }

    for (int it = 0; it < 8; it++) {
        int s = it & 3;
        CPWAIT2();           // stage it arrived (completed >= it+1 thanks to per-iter commits)
        __syncthreads();     // cross-thread visibility + buf-reuse safety

        uint32_t a[2][4], b[4][4];
        ldsm_x4(a[0], aaddr[s]);
        ldsm_x4(a[1], aaddr[s] + 16 * AST * 2);
#pragma unroll
        for (int g = 0; g < 4; g++)
            ldsm_x4_t(b[g], baddr[s] + g * 16 * 2);
#pragma unroll
        for (int ni = 0; ni < 8; ni++) {
            uint32_t b0 = b[ni >> 1][(ni & 1) * 2 + 0];
            uint32_t b1 = b[ni >> 1][(ni & 1) * 2 + 1];
            mma16816(acc[0][ni], a[0], b0, b1);
            mma16816(acc[1][ni], a[1], b0, b1);
        }

        int nx = it + 3;
        if (nx < 8) {
            int sn = nx & 3;
            cpasync16(adst[sn], axsrc + nx * KC);
            cpasync16(wdst[sn], wsrc + (size_t)nx * KC * HC);
        }
        CPCOMMIT();          // always commit (possibly empty) to keep group count uniform
    }

    // epilogue: store h1 (fp16) + partial attention dots (one head per warp)
    int r  = lane >> 2;
    int kq = lane & 3;
    int hbase = (c0 + wn * 64) >> 6;
    float sA[2][2] = {{0.f, 0.f}, {0.f, 0.f}};
    float dA[2][2] = {{0.f, 0.f}, {0.f, 0.f}};
#pragma unroll
    for (int mi = 0; mi < 2; mi++) {
        int row_lo = n0 + wm * 32 + mi * 16 + r;
        int row_hi = row_lo + 8;
#pragma unroll
        for (int ni = 0; ni < 8; ni++) {
            const float* dd = acc[mi][ni];
            int col = c0 + wn * 64 + ni * 8 + 2 * kq;
            if (row_lo < N) {
                uint32_t pv = packh2(dd[0], dd[1]);
                *(uint32_t*)&g_h1h[(size_t)row_lo * HC + col] = pv;
            }
            if (row_hi < N) {
                uint32_t pv = packh2(dd[2], dd[3]);
                *(uint32_t*)&g_h1h[(size_t)row_hi * HC + col] = pv;
            }
            float2 as = *(const float2*)&att_src[col];
            float2 ad = *(const float2*)&att_dst[col];
            sA[mi][0] += dd[0] * as.x + dd[1] * as.y;
            sA[mi][1] += dd[2] * as.x + dd[3] * as.y;
            dA[mi][0] += dd[0] * ad.x + dd[1] * ad.y;
            dA[mi][1] += dd[2] * ad.x + dd[3] * ad.y;
        }
    }
#pragma unroll
    for (int mi = 0; mi < 2; mi++)
#pragma unroll
        for (int j = 0; j < 2; j++) {
            sA[mi][j] += __shfl_down_sync(0xFFFFFFFFu, sA[mi][j], 2, 4);
            sA[mi][j] += __shfl_down_sync(0xFFFFFFFFu, sA[mi][j], 1, 4);
            dA[mi][j] += __shfl_down_sync(0xFFFFFFFFu, dA[mi][j], 2, 4);
            dA[mi][j] += __shfl_down_sync(0xFFFFFFFFu, dA[mi][j], 1, 4);
        }
    if (kq == 0) {
#pragma unroll
        for (int mi = 0; mi < 2; mi++)
#pragma unroll
            for (int j = 0; j < 2; j++) {
                int node = n0 + wm * 32 + mi * 16 + j * 8 + r;
                if (node < N) {
                    atomicAdd(&g_as1[node * H1 + hbase], sA[mi][j]);
                    atomicAdd(&g_ad1[node * H1 + hbase], dA[mi][j]);
                }
            }
    }
}

// ---- fused layer-1 softmax+aggregation+layer-2 projection -------------------
// One WARP per destination node; fp16 gather (16B/lane/edge), 4-edge unroll.
__global__ void agg1_kernel(const float* __restrict__ b1,
                            const float* __restrict__ W2,
                            const float* __restrict__ att_src2,
                            const float* __restrict__ att_dst2, int N) {
    int gid  = blockIdx.x * blockDim.x + threadIdx.x;
    int n    = gid >> 5;
    int lane = gid & 31;
    if (n >= N) return;
    int start = g_rowstart[n];
    int deg   = g_cnt[n];
    int cbase = lane * 8;
    int h     = lane >> 3;
    float ad  = g_ad1[n * 4 + h];

    float A[8];
#pragma unroll
    for (int j = 0; j < 8; j++) A[j] = 0.f;
    float den = 0.f;

    int e = 0;
    for (; e + 4 <= deg; e += 4) {
        int s0 = g_csr_src[start + e + 0];
        int s1 = g_csr_src[start + e + 1];
        int s2 = g_csr_src[start + e + 2];
        int s3 = g_csr_src[start + e + 3];
        float a0 = g_as1[s0 * 4 + h];
        float a1 = g_as1[s1 * 4 + h];
        float a2 = g_as1[s2 * 4 + h];
        float a3 = g_as1[s3 * 4 + h];
        uint4 v0 = *(const uint4*)&g_h1h[(size_t)s0 * HC + cbase];
        uint4 v1 = *(const uint4*)&g_h1h[(size_t)s1 * HC + cbase];
        uint4 v2 = *(const uint4*)&g_h1h[(size_t)s2 * HC + cbase];
        uint4 v3 = *(const uint4*)&g_h1h[(size_t)s3 * HC + cbase];
        float x0 = __expf(lrelu(a0 + ad));
        float x1 = __expf(lrelu(a1 + ad));
        float x2 = __expf(lrelu(a2 + ad));
        float x3 = __expf(lrelu(a3 + ad));
        den += (x0 + x1) + (x2 + x3);
        const uint32_t* vv[4] = {&v0.x, &v1.x, &v2.x, &v3.x};
        float xs[4] = {x0, x1, x2, x3};
#pragma unroll
        for (int q = 0; q < 4; q++) {
            float xq = xs[q];
#pragma unroll
            for (int j = 0; j < 4; j++) {
                float2 f = __half22float2(*(const __half2*)&vv[q][j]);
                A[2 * j + 0] += xq * f.x;
                A[2 * j + 1] += xq * f.y;
            }
        }
    }
    for (; e < deg; e++) {
        int s0 = g_csr_src[start + e];
        float a0 = g_as1[s0 * 4 + h];
        uint4 v0 = *(const uint4*)&g_h1h[(size_t)s0 * HC + cbase];
        float x0 = __expf(lrelu(a0 + ad));
        den += x0;
        const uint32_t* vv = &v0.x;
#pragma unroll
        for (int j = 0; j < 4; j++) {
            float2 f = __half22float2(*(const __half2*)&vv[j]);
            A[2 * j + 0] += x0 * f.x;
            A[2 * j + 1] += x0 * f.y;
        }
    }

    float inv = 1.f / (den + 1e-16f);
    const float4* b4 = (const float4*)&b1[cbase];
    float4 bb0 = b4[0], bb1 = b4[1];
    float y[8];
    y[0] = fmaxf(A[0] * inv + bb0.x, 0.f);
    y[1] = fmaxf(A[1] * inv + bb0.y, 0.f);
    y[2] = fmaxf(A[2] * inv + bb0.z, 0.f);
    y[3] = fmaxf(A[3] * inv + bb0.w, 0.f);
    y[4] = fmaxf(A[4] * inv + bb1.x, 0.f);
    y[5] = fmaxf(A[5] * inv + bb1.y, 0.f);
    y[6] = fmaxf(A[6] * inv + bb1.z, 0.f);
    y[7] = fmaxf(A[7] * inv + bb1.w, 0.f);

    const float4* w0q = (const float4*)&W2[cbase];
    const float4* w1q = (const float4*)&W2[HC + cbase];
    float4 wa0 = w0q[0], wa1 = w0q[1];
    float4 wb0 = w1q[0], wb1 = w1q[1];
    float p0 = y[0] * wa0.x + y[1] * wa0.y + y[2] * wa0.z + y[3] * wa0.w
             + y[4] * wa1.x + y[5] * wa1.y + y[6] * wa1.z + y[7] * wa1.w;
    float p1 = y[0] * wb0.x + y[1] * wb0.y + y[2] * wb0.z + y[3] * wb0.w
             + y[4] * wb1.x + y[5] * wb1.y + y[6] * wb1.z + y[7] * wb1.w;
#pragma unroll
    for (int o = 16; o; o >>= 1) {
        p0 += __shfl_down_sync(0xFFFFFFFFu, p0, o);
        p1 += __shfl_down_sync(0xFFFFFFFFu, p1, o);
    }
    if (lane == 0) {
        g_h2[n * 2 + 0] = p0;
        g_h2[n * 2 + 1] = p1;
        g_as2[n] = p0 * att_src2[0] + p1 * att_src2[1];
        g_ad2[n] = p0 * att_dst2[0] + p1 * att_dst2[1];
    }
}

// ---------------- fused layer-2: 8 lanes per destination node ---------------
__global__ void agg2_kernel(const float* __restrict__ b2,
                            float* __restrict__ out, int N) {
    int gid  = blockIdx.x * blockDim.x + threadIdx.x;
    int n    = gid >> 3;
    int lane = gid & 7;
    if (n >= N) return;
    int start = g_rowstart[n];
    int deg   = g_cnt[n];
    float adv = g_ad2[n];

    float den = 0.f, a0 = 0.f, a1 = 0.f;
    for (int e = lane; e < deg; e += 8) {
        int s  = g_csr_src[start + e];
        float ex = __expf(lrelu(g_as2[s] + adv));
        den += ex;
        float2 hv = *(const float2*)&g_h2[s * 2];
        a0 += ex * hv.x;
        a1 += ex * hv.y;
    }
#pragma unroll
    for (int o = 4; o; o >>= 1) {
        den += __shfl_xor_sync(0xFFFFFFFFu, den, o, 8);
        a0  += __shfl_xor_sync(0xFFFFFFFFu, a0, o, 8);
        a1  += __shfl_xor_sync(0xFFFFFFFFu, a1, o, 8);
    }
    if (lane == 0) {
        float inv = 1.f / (den + 1e-16f);
        out[n * 2 + 0] = a0 * inv + b2[0];
        out[n * 2 + 1] = a1 * inv + b2[1];
    }
}

// ---------------- launch ----------------
extern "C" void kernel_launch(void* const* d_in, const int* in_sizes, int n_in,
                              void* d_out, int out_size) {
    const float* x        = (const float*)d_in[0];
    const void*  ei       = d_in[1];
    const float* W1       = (const float*)d_in[2];
    const float* att_src1 = (const float*)d_in[3];
    const float* att_dst1 = (const float*)d_in[4];
    const float* b1       = (const float*)d_in[5];
    const float* W2       = (const float*)d_in[6];
    const float* att_src2 = (const float*)d_in[7];
    const float* att_dst2 = (const float*)d_in[8];
    const float* b2       = (const float*)d_in[9];

    int N  = in_sizes[0] / F_IN;
    int E  = in_sizes[1] / 2;
    int EA = E + N;

    const int B = 256;
    int gE = (EA + B - 1) / B;
    int nb = (N + SCB - 1) / SCB;
    int nx8 = ((N + 128) * F_IN / 8 + B - 1) / B;

    // Side stream + events (created once, host-side only).
    static cudaStream_t sB = 0;
    static cudaEvent_t  ev0 = 0, evB = 0;
    if (!sB) {
        cudaStreamCreateWithFlags(&sB, cudaStreamNonBlocking);
        cudaEventCreateWithFlags(&ev0, cudaEventDisableTiming);
        cudaEventCreateWithFlags(&evB, cudaEventDisableTiming);
    }

    // -------- fork FIRST: branch A has no upstream deps --------
    cudaEventRecord(ev0, 0);
    cudaStreamWaitEvent(sB, ev0, 0);
    xcvt_kernel<<<nx8, B, 0, sB>>>(x, N);                                  // branch A
    wtzero_kernel<<<(N * H1 + B - 1) / B, B, 0, sB>>>(W1, N);
    dim3 gg((N + BMt - 1) / BMt, HC / BNt);
    gemm1_kernel<<<gg, 256, 0, sB>>>(N, att_src1, att_dst1);
    cudaEventRecord(evB, sB);

    // -------- stream 0: edge-side prologue + CSR build (overlaps gemm) ------
    detect_kernel<<<1, 32>>>(ei, 2 * E, (long long)N);
    zerocnt_kernel<<<(N + B - 1) / B, B>>>(N);
    edges_hist_kernel<<<(2 * E + N + B - 1) / B, B>>>(ei, E, N);
    scan1_kernel<<<nb, SCB>>>(N);
    scan2_kernel<<<1, 256>>>(nb);
    scan3_kernel<<<(N + B - 1) / B, B>>>(N);
    scatter_kernel<<<gE, B>>>(EA);

    // -------- join + aggregation --------
    cudaStreamWaitEvent(0, evB, 0);
    agg1_kernel<<<(N * 32 + B - 1) / B, B>>>(b1, W2, att_src2, att_dst2, N);
    agg2_kernel<<<(N * 8 + B - 1) / B, B>>>(b2, (float*)d_out, N);
}